// round 16
// baseline (speedup 1.0000x reference)
#include <cuda_runtime.h>
#include <cuda_bf16.h>
#include <math.h>
#include <float.h>

#define N_NODES 50000
#define N_EDGES 1600000
#define N_MSG   (N_EDGES + N_NODES)
#define C_OUT   40

// ---------------- scratch (static device globals; no allocation) ----------------
__device__ __align__(256) unsigned int g_agg_u[N_NODES * 64]; // mapped-uint segment-max

// ---------------- helpers ----------------
__device__ __forceinline__ unsigned int fmap(float v) {
    unsigned int k = __float_as_uint(v);
    return ((int)k < 0) ? ~k : (k | 0x80000000u);
}
__device__ __forceinline__ float funmap(unsigned int k) {
    return (k & 0x80000000u) ? __uint_as_float(k & 0x7FFFFFFFu)
                             : __uint_as_float(~k);
}
// tf32 mma reads only bits [31:13]; raw f32 bits == RZ-truncated tf32.
__device__ __forceinline__ void mma_tf32(float (&c)[4],
                                         unsigned int a0, unsigned int a1,
                                         unsigned int a2, unsigned int a3,
                                         unsigned int b0, unsigned int b1) {
    asm volatile(
        "mma.sync.aligned.m16n8k8.row.col.f32.tf32.tf32.f32 "
        "{%0,%1,%2,%3}, {%4,%5,%6,%7}, {%8,%9}, {%0,%1,%2,%3};"
        : "+f"(c[0]), "+f"(c[1]), "+f"(c[2]), "+f"(c[3])
        : "r"(a0), "r"(a1), "r"(a2), "r"(a3), "r"(b0), "r"(b1));
}

// ---------------- kernel 1: edge MLP v4 (validated, unchanged) ----------------
#define W2PS 68
__global__ __launch_bounds__(256, 3) void k_edge_v4(
    const float* __restrict__ x,
    const float* __restrict__ pos,
    const int*   __restrict__ ei,
    const float* __restrict__ W1,
    const float* __restrict__ b1,
    const float* __restrict__ W2,
    const float* __restrict__ b2)
{
    __shared__ float sW1[6 * 64];
    __shared__ float sb1[64];
    __shared__ float sb2[64];
    __shared__ uint2 sW2p[32 * W2PS];
    __shared__ float sIn[256 * 9];
    __shared__ int   sdst[256];

    const int tid  = threadIdx.x;
    const int lane = tid & 31;
    const int warp = tid >> 5;
    const int g    = lane >> 2;
    const int tg   = lane & 3;

    for (int i = tid; i < 6 * 64; i += 256) sW1[i] = W1[i];
    if (tid < 64) { sb1[tid] = b1[tid]; sb2[tid] = b2[tid]; }
    for (int i = tid; i < 2048; i += 256) {
        int ks = i >> 8;
        int tt = (i >> 6) & 3;
        int n  = i & 63;
        float w0 = W2[(8 * ks + tt) * 64 + n];
        float w1 = W2[(8 * ks + tt + 4) * 64 + n];
        sW2p[(4 * ks + tt) * W2PS + n] = make_uint2(__float_as_uint(w0), __float_as_uint(w1));
    }

    const int m0 = blockIdx.x * 256;
    {
        int m = m0 + tid;
        int src = 0, dst = -1;
        if (m < N_MSG) {
            if (m < N_EDGES) { src = ei[m]; dst = ei[N_EDGES + m]; }
            else             { src = dst = m - N_EDGES; }
        }
        sdst[tid] = dst;
        float* ip = sIn + tid * 9;
        if (dst >= 0) {
            ip[0] = x[src * 3 + 0];
            ip[1] = x[src * 3 + 1];
            ip[2] = x[src * 3 + 2];
            ip[3] = pos[src * 3 + 0] - pos[dst * 3 + 0];
            ip[4] = pos[src * 3 + 1] - pos[dst * 3 + 1];
            ip[5] = pos[src * 3 + 2] - pos[dst * 3 + 2];
        } else {
            #pragma unroll
            for (int i = 0; i < 6; i++) ip[i] = 0.0f;
        }
    }
    __syncthreads();

    const int mrow = warp * 32;
    int mr[4];
    mr[0] = mrow + g; mr[1] = mr[0] + 8; mr[2] = mr[0] + 16; mr[3] = mr[0] + 24;

    float in[4][6];
    int d[4];
    #pragma unroll
    for (int r = 0; r < 4; r++) {
        d[r] = sdst[mr[r]];
        #pragma unroll
        for (int i = 0; i < 6; i++) in[r][i] = sIn[mr[r] * 9 + i];
    }

    #pragma unroll
    for (int pass = 0; pass < 2; pass++) {
        float c[2][4][4];
        #pragma unroll
        for (int mt = 0; mt < 2; mt++)
            #pragma unroll
            for (int nt = 0; nt < 4; nt++)
                #pragma unroll
                for (int q = 0; q < 4; q++) c[mt][nt][q] = 0.0f;

        #pragma unroll
        for (int ks = 0; ks < 8; ks++) {
            const int ka = 8 * ks + tg;
            const int kb = ka + 4;
            const float bka = sb1[ka], bkb = sb1[kb];
            float hA[4], hB[4];
            #pragma unroll
            for (int r = 0; r < 4; r++) { hA[r] = bka; hB[r] = bkb; }
            #pragma unroll
            for (int i = 0; i < 6; i++) {
                float wA = sW1[i * 64 + ka];
                float wB = sW1[i * 64 + kb];
                #pragma unroll
                for (int r = 0; r < 4; r++) {
                    hA[r] = fmaf(in[r][i], wA, hA[r]);
                    hB[r] = fmaf(in[r][i], wB, hB[r]);
                }
            }
            unsigned int af[2][4];
            #pragma unroll
            for (int mt = 0; mt < 2; mt++) {
                af[mt][0] = __float_as_uint(fmaxf(hA[2 * mt    ], 0.0f));
                af[mt][1] = __float_as_uint(fmaxf(hA[2 * mt + 1], 0.0f));
                af[mt][2] = __float_as_uint(fmaxf(hB[2 * mt    ], 0.0f));
                af[mt][3] = __float_as_uint(fmaxf(hB[2 * mt + 1], 0.0f));
            }
            const uint2* wrow = sW2p + (4 * ks + tg) * W2PS + pass * 32;
            #pragma unroll
            for (int nt = 0; nt < 4; nt++) {
                uint2 b = wrow[nt * 8 + g];
                mma_tf32(c[0][nt], af[0][0], af[0][1], af[0][2], af[0][3], b.x, b.y);
                mma_tf32(c[1][nt], af[1][0], af[1][1], af[1][2], af[1][3], b.x, b.y);
            }
        }

        #pragma unroll
        for (int mt = 0; mt < 2; mt++) {
            const int d0 = d[2 * mt];
            const int d1 = d[2 * mt + 1];
            #pragma unroll
            for (int nt = 0; nt < 4; nt++) {
                int ch = pass * 32 + nt * 8 + 2 * tg;
                float bv0 = sb2[ch], bv1 = sb2[ch + 1];
                if (d0 >= 0) {
                    atomicMax(g_agg_u + (size_t)d0 * 64 + ch,     fmap(c[mt][nt][0] + bv0));
                    atomicMax(g_agg_u + (size_t)d0 * 64 + ch + 1, fmap(c[mt][nt][1] + bv1));
                }
                if (d1 >= 0) {
                    atomicMax(g_agg_u + (size_t)d1 * 64 + ch,     fmap(c[mt][nt][2] + bv0));
                    atomicMax(g_agg_u + (size_t)d1 * 64 + ch + 1, fmap(c[mt][nt][3] + bv1));
                }
            }
        }
    }
}

// ---------------- fused mid v2: software-pipelined, 16x 64-col chunks ----------------
// 512 threads / 16 warps (wm 0..3 = 32-row groups, wn 0..3 = col groups).
// smem word offsets:
#define FS_G1 0                     // g1 tile [128][132]
#define FS_W4 16896                 // W3 [64][136] (pre-stage) / W4 sub [128][72] / Wf [64*40]
#define FS_W5 26112                 // W5 sub [64][72]
#define FS_T  30720                 // agg [128][68] -> t tile [128][68] -> g3 [128][68]
#define FS_BB 39424                 // b4 full [1024]
#define FS_B4 40448                 // b3 [128] / bf [40]
#define FS_B5 40576                 // b5 [64]
#define FS_WORDS 40640              // 162,560 bytes dynamic smem
#define FT 512
#define NCH 16

__global__ __launch_bounds__(FT) void k_fused_mid(
    const unsigned int* __restrict__ Agg, // mapped-uint agg [nrows,64]
    const float* __restrict__ W3,   // [64,128]
    const float* __restrict__ b3,   // [128]
    const float* __restrict__ W4,   // [128,1024]
    const float* __restrict__ b4,   // [1024]
    const float* __restrict__ W5,   // [1024,64]
    const float* __restrict__ b5,   // [64]
    const float* __restrict__ Wf,   // [64,40]
    const float* __restrict__ bf,   // [40]
    float* __restrict__ out,        // [nrows,40]
    int nrows)
{
    extern __shared__ unsigned int sm[];
    const int tid  = threadIdx.x;
    const int lane = tid & 31;
    const int warp = tid >> 5;
    const int wm   = warp >> 2;
    const int wn   = warp & 3;
    const int g    = lane >> 2;
    const int tg   = lane & 3;
    const int mrow = wm * 32;
    const int n0   = blockIdx.x * 128;

    // prefetch registers for one (W4 sub, W5 sub) chunk
    uint4 pw4[4], pw5[2];
    const int pk4 = tid >> 4;          // W4 row for uint4 idx base (idx = tid + i*512)
    const int pq  = tid & 15;

    // ---- issue chunk-0 prefetch FIRST (overlaps all staging below) ----
    #pragma unroll
    for (int i = 0; i < 4; i++) {
        int k = pk4 + i * 32;          // (tid + i*512) >> 4
        pw4[i] = *(const uint4*)&W4[(size_t)k * 1024 + 0 * 64 + pq * 4];
    }
    #pragma unroll
    for (int i = 0; i < 2; i++) {
        int k = pk4 + i * 32;
        pw5[i] = *(const uint4*)&W5[(size_t)(0 * 64 + k) * 64 + pq * 4];
    }

    // ---- stage agg tile [128][68] (unmapped) into FS_T ----
    #pragma unroll
    for (int i = 0; i < 16; i++) {
        int idx = tid + i * FT;
        int mm = idx >> 6, q = idx & 63;
        int row = n0 + mm;
        float v = 0.0f;
        if (row < nrows) v = funmap(Agg[(size_t)row * 64 + q]);
        sm[FS_T + mm * 68 + q] = __float_as_uint(v);
    }
    // ---- stage W3 [64][136] into FS_W4 region; biases ----
    #pragma unroll
    for (int i = 0; i < 4; i++) {
        int idx = tid + i * FT;
        int k = idx >> 5, q = idx & 31;
        *(uint4*)&sm[FS_W4 + k * 136 + q * 4] = *(const uint4*)&W3[(size_t)k * 128 + q * 4];
    }
    #pragma unroll
    for (int i = 0; i < 2; i++) sm[FS_BB + tid + i * FT] = __float_as_uint(b4[tid + i * FT]);
    if (tid < 128) sm[FS_B4 + tid] = __float_as_uint(b3[tid]);
    if (tid >= 128 && tid < 192) sm[FS_B5 + tid - 128] = __float_as_uint(b5[tid - 128]);
    __syncthreads();

    // ---- pre-stage: g1 = relu(agg @ W3 + b3) -> FS_G1 [128][132] ----
    {
        float acc[2][4][4];
        #pragma unroll
        for (int mt = 0; mt < 2; mt++)
            #pragma unroll
            for (int nt = 0; nt < 4; nt++)
                #pragma unroll
                for (int q = 0; q < 4; q++) acc[mt][nt][q] = 0.0f;

        #pragma unroll
        for (int ks = 0; ks < 8; ks++) {
            const int k0 = ks * 8;
            unsigned int a[2][4];
            #pragma unroll
            for (int mt = 0; mt < 2; mt++) {
                int mr = mrow + mt * 16;
                a[mt][0] = sm[FS_T + (mr + g    ) * 68 + k0 + tg    ];
                a[mt][1] = sm[FS_T + (mr + g + 8) * 68 + k0 + tg    ];
                a[mt][2] = sm[FS_T + (mr + g    ) * 68 + k0 + tg + 4];
                a[mt][3] = sm[FS_T + (mr + g + 8) * 68 + k0 + tg + 4];
            }
            #pragma unroll
            for (int nt = 0; nt < 4; nt++) {
                int nc = wn * 32 + nt * 8 + g;
                unsigned int b0 = sm[FS_W4 + (k0 + tg    ) * 136 + nc];
                unsigned int b1 = sm[FS_W4 + (k0 + tg + 4) * 136 + nc];
                #pragma unroll
                for (int mt = 0; mt < 2; mt++)
                    mma_tf32(acc[mt][nt], a[mt][0], a[mt][1], a[mt][2], a[mt][3], b0, b1);
            }
        }
        __syncthreads();   // agg (FS_T) + W3 (FS_W4) reads complete

        #pragma unroll
        for (int nt = 0; nt < 4; nt++) {
            int col = wn * 32 + nt * 8 + 2 * tg;
            float bv0 = __uint_as_float(sm[FS_B4 + col]);
            float bv1 = __uint_as_float(sm[FS_B4 + col + 1]);
            #pragma unroll
            for (int mt = 0; mt < 2; mt++) {
                int r0 = mrow + mt * 16 + g;
                int r1 = r0 + 8;
                sm[FS_G1 + r0 * 132 + col    ] = __float_as_uint(fmaxf(acc[mt][nt][0] + bv0, 0.0f));
                sm[FS_G1 + r0 * 132 + col + 1] = __float_as_uint(fmaxf(acc[mt][nt][1] + bv1, 0.0f));
                sm[FS_G1 + r1 * 132 + col    ] = __float_as_uint(fmaxf(acc[mt][nt][2] + bv0, 0.0f));
                sm[FS_G1 + r1 * 132 + col + 1] = __float_as_uint(fmaxf(acc[mt][nt][3] + bv1, 0.0f));
            }
        }
    }

    float acc2[2][2][4];   // persistent g3 accumulator: rows mrow+mt*16, cols wn*16+nt*8
    #pragma unroll
    for (int mt = 0; mt < 2; mt++)
        #pragma unroll
        for (int nt = 0; nt < 2; nt++)
            #pragma unroll
            for (int q = 0; q < 4; q++) acc2[mt][nt][q] = 0.0f;

    for (int cch = 0; cch < NCH; cch++) {
        __syncthreads();   // prior stage2 done reading FS_W5 / FS_T; g1 visible (iter 0)

        // store prefetched chunk to smem
        #pragma unroll
        for (int i = 0; i < 4; i++) {
            int k = pk4 + i * 32;
            *(uint4*)&sm[FS_W4 + k * 72 + pq * 4] = pw4[i];
        }
        #pragma unroll
        for (int i = 0; i < 2; i++) {
            int k = pk4 + i * 32;
            *(uint4*)&sm[FS_W5 + k * 72 + pq * 4] = pw5[i];
        }
        __syncthreads();

        // issue next chunk's loads (latency hidden under mma below)
        if (cch + 1 < NCH) {
            #pragma unroll
            for (int i = 0; i < 4; i++) {
                int k = pk4 + i * 32;
                pw4[i] = *(const uint4*)&W4[(size_t)k * 1024 + (cch + 1) * 64 + pq * 4];
            }
            #pragma unroll
            for (int i = 0; i < 2; i++) {
                int k = pk4 + i * 32;
                pw5[i] = *(const uint4*)&W5[(size_t)((cch + 1) * 64 + k) * 64 + pq * 4];
            }
        }

        // ---- stage1: t = g1 @ W4sub (128x64, K=128); warp cols wn*16 + nt*8 ----
        float acc1[2][2][4];
        #pragma unroll
        for (int mt = 0; mt < 2; mt++)
            #pragma unroll
            for (int nt = 0; nt < 2; nt++)
                #pragma unroll
                for (int q = 0; q < 4; q++) acc1[mt][nt][q] = 0.0f;

        #pragma unroll
        for (int ks = 0; ks < 16; ks++) {
            const int k0 = ks * 8;
            unsigned int a[2][4];
            #pragma unroll
            for (int mt = 0; mt < 2; mt++) {
                int mr = mrow + mt * 16;
                a[mt][0] = sm[FS_G1 + (mr + g    ) * 132 + k0 + tg    ];
                a[mt][1] = sm[FS_G1 + (mr + g + 8) * 132 + k0 + tg    ];
                a[mt][2] = sm[FS_G1 + (mr + g    ) * 132 + k0 + tg + 4];
                a[mt][3] = sm[FS_G1 + (mr + g + 8) * 132 + k0 + tg + 4];
            }
            #pragma unroll
            for (int nt = 0; nt < 2; nt++) {
                int nc = wn * 16 + nt * 8 + g;
                unsigned int b0 = sm[FS_W4 + (k0 + tg    ) * 72 + nc];
                unsigned int b1 = sm[FS_W4 + (k0 + tg + 4) * 72 + nc];
                #pragma unroll
                for (int mt = 0; mt < 2; mt++)
                    mma_tf32(acc1[mt][nt], a[mt][0], a[mt][1], a[mt][2], a[mt][3], b0, b1);
            }
        }

        // ---- bias + relu -> t tile FS_T [128][68] ----
        #pragma unroll
        for (int nt = 0; nt < 2; nt++) {
            int col = wn * 16 + nt * 8 + 2 * tg;                 // chunk-local col
            float bv0 = __uint_as_float(sm[FS_BB + cch * 64 + col]);
            float bv1 = __uint_as_float(sm[FS_BB + cch * 64 + col + 1]);
            #pragma unroll
            for (int mt = 0; mt < 2; mt++) {
                int r0 = mrow + mt * 16 + g;
                int r1 = r0 + 8;
                sm[FS_T + r0 * 68 + col    ] = __float_as_uint(fmaxf(acc1[mt][nt][0] + bv0, 0.0f));
                sm[FS_T + r0 * 68 + col + 1] = __float_as_uint(fmaxf(acc1[mt][nt][1] + bv1, 0.0f));
                sm[FS_T + r1 * 68 + col    ] = __float_as_uint(fmaxf(acc1[mt][nt][2] + bv0, 0.0f));
                sm[FS_T + r1 * 68 + col + 1] = __float_as_uint(fmaxf(acc1[mt][nt][3] + bv1, 0.0f));
            }
        }
        __syncthreads();

        // ---- stage2: acc2 += t @ W5sub (128x64, K=64) ----
        #pragma unroll
        for (int ks = 0; ks < 8; ks++) {
            const int k0 = ks * 8;
            unsigned int a[2][4];
            #pragma unroll
            for (int mt = 0; mt < 2; mt++) {
                int mr = mrow + mt * 16;
                a[mt][0] = sm[FS_T + (mr + g    ) * 68 + k0 + tg    ];
                a[mt][1] = sm[FS_T + (mr + g + 8) * 68 + k0 + tg    ];
                a[mt][2] = sm[FS_T + (mr + g    ) * 68 + k0 + tg + 4];
                a[mt][3] = sm[FS_T + (mr + g + 8) * 68 + k0 + tg + 4];
            }
            #pragma unroll
            for (int nt = 0; nt < 2; nt++) {
                int nc = wn * 16 + nt * 8 + g;
                unsigned int b0 = sm[FS_W5 + (k0 + tg    ) * 72 + nc];
                unsigned int b1 = sm[FS_W5 + (k0 + tg + 4) * 72 + nc];
                #pragma unroll
                for (int mt = 0; mt < 2; mt++)
                    mma_tf32(acc2[mt][nt], a[mt][0], a[mt][1], a[mt][2], a[mt][3], b0, b1);
            }
        }
    }
    __syncthreads();   // stage2[15] done with FS_T / FS_W5

    // ---- fc staging: Wf -> FS_W4, bf -> FS_B4; g3 (+b5) -> FS_T stride 68 ----
    for (int i = tid; i < 64 * 40; i += FT) sm[FS_W4 + i] = __float_as_uint(Wf[i]);
    if (tid < 40) sm[FS_B4 + tid] = __float_as_uint(bf[tid]);
    #pragma unroll
    for (int nt = 0; nt < 2; nt++) {
        int col = wn * 16 + nt * 8 + 2 * tg;
        float bv0 = __uint_as_float(sm[FS_B5 + col]);
        float bv1 = __uint_as_float(sm[FS_B5 + col + 1]);
        #pragma unroll
        for (int mt = 0; mt < 2; mt++) {
            int r0 = mrow + mt * 16 + g;
            int r1 = r0 + 8;
            sm[FS_T + r0 * 68 + col    ] = __float_as_uint(acc2[mt][nt][0] + bv0);
            sm[FS_T + r0 * 68 + col + 1] = __float_as_uint(acc2[mt][nt][1] + bv1);
            sm[FS_T + r1 * 68 + col    ] = __float_as_uint(acc2[mt][nt][2] + bv0);
            sm[FS_T + r1 * 68 + col + 1] = __float_as_uint(acc2[mt][nt][3] + bv1);
        }
    }
    __syncthreads();

    // ---- fc + log_softmax: 16 warps x 8 nodes ----
    for (int j = 0; j < 8; j++) {
        int nl = warp * 8 + j;
        int node = n0 + nl;
        if (node >= nrows) break;
        float v0 = __uint_as_float(sm[FS_B4 + lane]);
        float v1 = (lane < 8) ? __uint_as_float(sm[FS_B4 + lane + 32]) : -FLT_MAX;
        #pragma unroll
        for (int k = 0; k < 64; k++) {
            float a = fmaxf(__uint_as_float(sm[FS_T + nl * 68 + k]), 0.0f);
            float w0 = __uint_as_float(sm[FS_W4 + k * 40 + lane]);
            v0 = fmaf(a, w0, v0);
            if (lane < 8) {
                float w1 = __uint_as_float(sm[FS_W4 + k * 40 + lane + 32]);
                v1 = fmaf(a, w1, v1);
            }
        }
        float mx = fmaxf(v0, v1);
        #pragma unroll
        for (int off = 16; off > 0; off >>= 1)
            mx = fmaxf(mx, __shfl_xor_sync(0xFFFFFFFFu, mx, off));
        float s = __expf(v0 - mx) + ((lane < 8) ? __expf(v1 - mx) : 0.0f);
        #pragma unroll
        for (int off = 16; off > 0; off >>= 1)
            s += __shfl_xor_sync(0xFFFFFFFFu, s, off);
        float ls = __logf(s);
        float* op = out + (size_t)node * C_OUT;
        op[lane] = v0 - mx - ls;
        if (lane < 8) op[lane + 32] = v1 - mx - ls;
    }
}

// ---------------- launcher ----------------
extern "C" void kernel_launch(void* const* d_in, const int* in_sizes, int n_in,
                              void* d_out, int out_size) {
    const float* x   = (const float*)d_in[0];
    const float* pos = (const float*)d_in[1];
    const int*   ei  = (const int*)d_in[2];
    const float* W1 = (const float*)d_in[3];
    const float* b1 = (const float*)d_in[4];
    const float* W2 = (const float*)d_in[5];
    const float* b2 = (const float*)d_in[6];
    const float* W3 = (const float*)d_in[7];
    const float* b3 = (const float*)d_in[8];
    const float* W4 = (const float*)d_in[9];
    const float* b4 = (const float*)d_in[10];
    const float* W5 = (const float*)d_in[11];
    const float* b5 = (const float*)d_in[12];
    const float* Wf = (const float*)d_in[13];
    const float* bf = (const float*)d_in[14];
    float* out = (float*)d_out;

    void* aggp = nullptr;
    cudaGetSymbolAddress(&aggp, g_agg_u);

    cudaFuncSetAttribute(k_fused_mid, cudaFuncAttributeMaxDynamicSharedMemorySize,
                         FS_WORDS * 4);

    // mapped-uint 0 is below every mapped float -> -inf init
    cudaMemsetAsync(aggp, 0, (size_t)N_NODES * 64 * sizeof(unsigned int));

    k_edge_v4<<<(N_MSG + 255) / 256, 256>>>(x, pos, ei, W1, b1, W2, b2);

    k_fused_mid<<<(N_NODES + 127) / 128, FT, FS_WORDS * 4>>>(
        (const unsigned int*)aggp, W3, b3, W4, b4, W5, b5, Wf, bf, out, N_NODES);
}

// round 17
// speedup vs baseline: 1.0212x; 1.0212x over previous
#include <cuda_runtime.h>
#include <cuda_bf16.h>
#include <math.h>
#include <float.h>

#define N_NODES 50000
#define N_EDGES 1600000
#define N_MSG   (N_EDGES + N_NODES)
#define C_OUT   40

// ---------------- scratch (static device globals; no allocation) ----------------
__device__ __align__(256) unsigned int g_agg_u[N_NODES * 64]; // mapped-uint segment-max

// ---------------- helpers ----------------
__device__ __forceinline__ unsigned int fmap(float v) {
    unsigned int k = __float_as_uint(v);
    return ((int)k < 0) ? ~k : (k | 0x80000000u);
}
__device__ __forceinline__ float funmap(unsigned int k) {
    return (k & 0x80000000u) ? __uint_as_float(k & 0x7FFFFFFFu)
                             : __uint_as_float(~k);
}
// tf32 mma reads only bits [31:13]; raw f32 bits == RZ-truncated tf32.
__device__ __forceinline__ void mma_tf32(float (&c)[4],
                                         unsigned int a0, unsigned int a1,
                                         unsigned int a2, unsigned int a3,
                                         unsigned int b0, unsigned int b1) {
    asm volatile(
        "mma.sync.aligned.m16n8k8.row.col.f32.tf32.tf32.f32 "
        "{%0,%1,%2,%3}, {%4,%5,%6,%7}, {%8,%9}, {%0,%1,%2,%3};"
        : "+f"(c[0]), "+f"(c[1]), "+f"(c[2]), "+f"(c[3])
        : "r"(a0), "r"(a1), "r"(a2), "r"(a3), "r"(b0), "r"(b1));
}

// Fragment-packed ("permuted") tile layout.
// uint4 index for the A-fragment of (k-step ks, thread tg, 16-row group mrg, row g):
//   U = (ks*4+tg)*66 + mrg*8 + g        (stride 66 uint4 == 2 mod 8 bank groups -> conflict-free LDS.128)
// components: [0]=(row g, k lo) [1]=(row g+8, k lo) [2]=(row g, k hi) [3]=(row g+8, k hi)
__device__ __forceinline__ int pfrag_u4(int ks, int tg, int mrg, int g) {
    return ((ks * 4 + tg) * 66 + mrg * 8 + g) * 4;
}
// scalar word address for element (row r, col c) in a fragment-packed tile
__device__ __forceinline__ int pfrag_w(int base, int r, int c) {
    return base + (((c >> 3) * 4 + (c & 3)) * 66 + (r >> 4) * 8 + (r & 7)) * 4
                + ((r >> 3) & 1) + 2 * ((c >> 2) & 1);
}

// ---------------- kernel 1: edge MLP v4 (validated, unchanged) ----------------
#define W2PS 68
__global__ __launch_bounds__(256, 3) void k_edge_v4(
    const float* __restrict__ x,
    const float* __restrict__ pos,
    const int*   __restrict__ ei,
    const float* __restrict__ W1,
    const float* __restrict__ b1,
    const float* __restrict__ W2,
    const float* __restrict__ b2)
{
    __shared__ float sW1[6 * 64];
    __shared__ float sb1[64];
    __shared__ float sb2[64];
    __shared__ uint2 sW2p[32 * W2PS];
    __shared__ float sIn[256 * 9];
    __shared__ int   sdst[256];

    const int tid  = threadIdx.x;
    const int lane = tid & 31;
    const int warp = tid >> 5;
    const int g    = lane >> 2;
    const int tg   = lane & 3;

    for (int i = tid; i < 6 * 64; i += 256) sW1[i] = W1[i];
    if (tid < 64) { sb1[tid] = b1[tid]; sb2[tid] = b2[tid]; }
    for (int i = tid; i < 2048; i += 256) {
        int ks = i >> 8;
        int tt = (i >> 6) & 3;
        int n  = i & 63;
        float w0 = W2[(8 * ks + tt) * 64 + n];
        float w1 = W2[(8 * ks + tt + 4) * 64 + n];
        sW2p[(4 * ks + tt) * W2PS + n] = make_uint2(__float_as_uint(w0), __float_as_uint(w1));
    }

    const int m0 = blockIdx.x * 256;
    {
        int m = m0 + tid;
        int src = 0, dst = -1;
        if (m < N_MSG) {
            if (m < N_EDGES) { src = ei[m]; dst = ei[N_EDGES + m]; }
            else             { src = dst = m - N_EDGES; }
        }
        sdst[tid] = dst;
        float* ip = sIn + tid * 9;
        if (dst >= 0) {
            ip[0] = x[src * 3 + 0];
            ip[1] = x[src * 3 + 1];
            ip[2] = x[src * 3 + 2];
            ip[3] = pos[src * 3 + 0] - pos[dst * 3 + 0];
            ip[4] = pos[src * 3 + 1] - pos[dst * 3 + 1];
            ip[5] = pos[src * 3 + 2] - pos[dst * 3 + 2];
        } else {
            #pragma unroll
            for (int i = 0; i < 6; i++) ip[i] = 0.0f;
        }
    }
    __syncthreads();

    const int mrow = warp * 32;
    int mr[4];
    mr[0] = mrow + g; mr[1] = mr[0] + 8; mr[2] = mr[0] + 16; mr[3] = mr[0] + 24;

    float in[4][6];
    int d[4];
    #pragma unroll
    for (int r = 0; r < 4; r++) {
        d[r] = sdst[mr[r]];
        #pragma unroll
        for (int i = 0; i < 6; i++) in[r][i] = sIn[mr[r] * 9 + i];
    }

    #pragma unroll
    for (int pass = 0; pass < 2; pass++) {
        float c[2][4][4];
        #pragma unroll
        for (int mt = 0; mt < 2; mt++)
            #pragma unroll
            for (int nt = 0; nt < 4; nt++)
                #pragma unroll
                for (int q = 0; q < 4; q++) c[mt][nt][q] = 0.0f;

        #pragma unroll
        for (int ks = 0; ks < 8; ks++) {
            const int ka = 8 * ks + tg;
            const int kb = ka + 4;
            const float bka = sb1[ka], bkb = sb1[kb];
            float hA[4], hB[4];
            #pragma unroll
            for (int r = 0; r < 4; r++) { hA[r] = bka; hB[r] = bkb; }
            #pragma unroll
            for (int i = 0; i < 6; i++) {
                float wA = sW1[i * 64 + ka];
                float wB = sW1[i * 64 + kb];
                #pragma unroll
                for (int r = 0; r < 4; r++) {
                    hA[r] = fmaf(in[r][i], wA, hA[r]);
                    hB[r] = fmaf(in[r][i], wB, hB[r]);
                }
            }
            unsigned int af[2][4];
            #pragma unroll
            for (int mt = 0; mt < 2; mt++) {
                af[mt][0] = __float_as_uint(fmaxf(hA[2 * mt    ], 0.0f));
                af[mt][1] = __float_as_uint(fmaxf(hA[2 * mt + 1], 0.0f));
                af[mt][2] = __float_as_uint(fmaxf(hB[2 * mt    ], 0.0f));
                af[mt][3] = __float_as_uint(fmaxf(hB[2 * mt + 1], 0.0f));
            }
            const uint2* wrow = sW2p + (4 * ks + tg) * W2PS + pass * 32;
            #pragma unroll
            for (int nt = 0; nt < 4; nt++) {
                uint2 b = wrow[nt * 8 + g];
                mma_tf32(c[0][nt], af[0][0], af[0][1], af[0][2], af[0][3], b.x, b.y);
                mma_tf32(c[1][nt], af[1][0], af[1][1], af[1][2], af[1][3], b.x, b.y);
            }
        }

        #pragma unroll
        for (int mt = 0; mt < 2; mt++) {
            const int d0 = d[2 * mt];
            const int d1 = d[2 * mt + 1];
            #pragma unroll
            for (int nt = 0; nt < 4; nt++) {
                int ch = pass * 32 + nt * 8 + 2 * tg;
                float bv0 = sb2[ch], bv1 = sb2[ch + 1];
                if (d0 >= 0) {
                    atomicMax(g_agg_u + (size_t)d0 * 64 + ch,     fmap(c[mt][nt][0] + bv0));
                    atomicMax(g_agg_u + (size_t)d0 * 64 + ch + 1, fmap(c[mt][nt][1] + bv1));
                }
                if (d1 >= 0) {
                    atomicMax(g_agg_u + (size_t)d1 * 64 + ch,     fmap(c[mt][nt][2] + bv0));
                    atomicMax(g_agg_u + (size_t)d1 * 64 + ch + 1, fmap(c[mt][nt][3] + bv1));
                }
            }
        }
    }
}

// ---------------- fused mid v3: fragment-packed tiles, 16x 64-col chunks ----------------
// 512 threads / 16 warps (wm 0..3 = 32-row groups, wn 0..3 = col groups).
// smem word offsets:
#define FS_G1 0                     // g1 tile, fragment-packed K=128: 64*66*4 = 16896
#define FS_W4 16896                 // W3 [64][136] (pre-stage) / W4 sub [128][72] / Wf [64*40]
#define FS_W5 26112                 // W5 sub [64][72]
#define FS_T  30720                 // fragment-packed K=64 tile: 32*66*4 = 8448 (agg -> t -> g3)
#define FS_BB 39168                 // b4 full [1024]
#define FS_B4 40192                 // b3 [128] / bf [40]
#define FS_B5 40320                 // b5 [64]
#define FS_WORDS 40384              // 161,536 bytes dynamic smem
#define FT 512
#define NCH 16

__global__ __launch_bounds__(FT) void k_fused_mid(
    const unsigned int* __restrict__ Agg, // mapped-uint agg [nrows,64]
    const float* __restrict__ W3,   // [64,128]
    const float* __restrict__ b3,   // [128]
    const float* __restrict__ W4,   // [128,1024]
    const float* __restrict__ b4,   // [1024]
    const float* __restrict__ W5,   // [1024,64]
    const float* __restrict__ b5,   // [64]
    const float* __restrict__ Wf,   // [64,40]
    const float* __restrict__ bf,   // [40]
    float* __restrict__ out,        // [nrows,40]
    int nrows)
{
    extern __shared__ unsigned int sm[];
    const int tid  = threadIdx.x;
    const int lane = tid & 31;
    const int warp = tid >> 5;
    const int wm   = warp >> 2;
    const int wn   = warp & 3;
    const int g    = lane >> 2;
    const int tg   = lane & 3;
    const int mrow = wm * 32;
    const int n0   = blockIdx.x * 128;

    // ---- stage agg tile (unmapped) into fragment-packed FS_T ----
    #pragma unroll
    for (int i = 0; i < 16; i++) {
        int idx = tid + i * FT;
        int mm = idx >> 6, q = idx & 63;
        int row = n0 + mm;
        float v = 0.0f;
        if (row < nrows) v = funmap(Agg[(size_t)row * 64 + q]);
        sm[pfrag_w(FS_T, mm, q)] = __float_as_uint(v);
    }
    // ---- stage W3 [64][136] into FS_W4 region; biases ----
    #pragma unroll
    for (int i = 0; i < 4; i++) {
        int idx = tid + i * FT;
        int k = idx >> 5, q = idx & 31;
        *(uint4*)&sm[FS_W4 + k * 136 + q * 4] = *(const uint4*)&W3[(size_t)k * 128 + q * 4];
    }
    #pragma unroll
    for (int i = 0; i < 2; i++) sm[FS_BB + tid + i * FT] = __float_as_uint(b4[tid + i * FT]);
    if (tid < 128) sm[FS_B4 + tid] = __float_as_uint(b3[tid]);
    if (tid >= 128 && tid < 192) sm[FS_B5 + tid - 128] = __float_as_uint(b5[tid - 128]);
    __syncthreads();

    // ---- pre-stage: g1 = relu(agg @ W3 + b3) -> fragment-packed FS_G1 ----
    {
        float acc[2][4][4];
        #pragma unroll
        for (int mt = 0; mt < 2; mt++)
            #pragma unroll
            for (int nt = 0; nt < 4; nt++)
                #pragma unroll
                for (int q = 0; q < 4; q++) acc[mt][nt][q] = 0.0f;

        #pragma unroll
        for (int ks = 0; ks < 8; ks++) {
            const int k0 = ks * 8;
            uint4 a[2];
            #pragma unroll
            for (int mt = 0; mt < 2; mt++)
                a[mt] = *(const uint4*)&sm[FS_T + pfrag_u4(ks, tg, wm * 2 + mt, g)];
            #pragma unroll
            for (int nt = 0; nt < 4; nt++) {
                int nc = wn * 32 + nt * 8 + g;
                unsigned int b0 = sm[FS_W4 + (k0 + tg    ) * 136 + nc];
                unsigned int b1 = sm[FS_W4 + (k0 + tg + 4) * 136 + nc];
                #pragma unroll
                for (int mt = 0; mt < 2; mt++)
                    mma_tf32(acc[mt][nt], a[mt].x, a[mt].y, a[mt].z, a[mt].w, b0, b1);
            }
        }
        __syncthreads();   // agg (FS_T) + W3 (FS_W4) reads complete

        #pragma unroll
        for (int nt = 0; nt < 4; nt++) {
            int col = wn * 32 + nt * 8 + 2 * tg;
            float bv0 = __uint_as_float(sm[FS_B4 + col]);
            float bv1 = __uint_as_float(sm[FS_B4 + col + 1]);
            #pragma unroll
            for (int mt = 0; mt < 2; mt++) {
                int r0 = mrow + mt * 16 + g;
                int r1 = r0 + 8;
                sm[pfrag_w(FS_G1, r0, col    )] = __float_as_uint(fmaxf(acc[mt][nt][0] + bv0, 0.0f));
                sm[pfrag_w(FS_G1, r0, col + 1)] = __float_as_uint(fmaxf(acc[mt][nt][1] + bv1, 0.0f));
                sm[pfrag_w(FS_G1, r1, col    )] = __float_as_uint(fmaxf(acc[mt][nt][2] + bv0, 0.0f));
                sm[pfrag_w(FS_G1, r1, col + 1)] = __float_as_uint(fmaxf(acc[mt][nt][3] + bv1, 0.0f));
            }
        }
    }

    float acc2[2][2][4];   // persistent g3 accumulator: rows mrow+mt*16, cols wn*16+nt*8
    #pragma unroll
    for (int mt = 0; mt < 2; mt++)
        #pragma unroll
        for (int nt = 0; nt < 2; nt++)
            #pragma unroll
            for (int q = 0; q < 4; q++) acc2[mt][nt][q] = 0.0f;

    for (int cch = 0; cch < NCH; cch++) {
        __syncthreads();   // prior stage2 done with FS_W4/FS_W5/FS_T; g1 visible (iter 0)

        // ---- cooperative load of chunk weights ----
        #pragma unroll
        for (int i = 0; i < 4; i++) {          // W4 sub: 128 x 64 -> [k][72]
            int idx = tid + i * FT;            // 0..2047 uint4
            int k = idx >> 4, q = idx & 15;
            *(uint4*)&sm[FS_W4 + k * 72 + q * 4] =
                *(const uint4*)&W4[(size_t)k * 1024 + cch * 64 + q * 4];
        }
        #pragma unroll
        for (int i = 0; i < 2; i++) {          // W5 sub: 64 x 64 -> [k][72]
            int idx = tid + i * FT;            // 0..1023 uint4
            int k = idx >> 4, q = idx & 15;
            *(uint4*)&sm[FS_W5 + k * 72 + q * 4] =
                *(const uint4*)&W5[(size_t)(cch * 64 + k) * 64 + q * 4];
        }
        __syncthreads();

        // ---- stage1: t = g1 @ W4sub (128x64, K=128); warp cols wn*16 + nt*8 ----
        float acc1[2][2][4];
        #pragma unroll
        for (int mt = 0; mt < 2; mt++)
            #pragma unroll
            for (int nt = 0; nt < 2; nt++)
                #pragma unroll
                for (int q = 0; q < 4; q++) acc1[mt][nt][q] = 0.0f;

        #pragma unroll
        for (int ks = 0; ks < 16; ks++) {
            const int k0 = ks * 8;
            uint4 a[2];
            #pragma unroll
            for (int mt = 0; mt < 2; mt++)
                a[mt] = *(const uint4*)&sm[FS_G1 + pfrag_u4(ks, tg, wm * 2 + mt, g)];
            #pragma unroll
            for (int nt = 0; nt < 2; nt++) {
                int nc = wn * 16 + nt * 8 + g;
                unsigned int b0 = sm[FS_W4 + (k0 + tg    ) * 72 + nc];
                unsigned int b1 = sm[FS_W4 + (k0 + tg + 4) * 72 + nc];
                #pragma unroll
                for (int mt = 0; mt < 2; mt++)
                    mma_tf32(acc1[mt][nt], a[mt].x, a[mt].y, a[mt].z, a[mt].w, b0, b1);
            }
        }

        // ---- bias + relu -> fragment-packed t tile (FS_T) ----
        #pragma unroll
        for (int nt = 0; nt < 2; nt++) {
            int col = wn * 16 + nt * 8 + 2 * tg;                 // chunk-local col 0..63
            float bv0 = __uint_as_float(sm[FS_BB + cch * 64 + col]);
            float bv1 = __uint_as_float(sm[FS_BB + cch * 64 + col + 1]);
            #pragma unroll
            for (int mt = 0; mt < 2; mt++) {
                int r0 = mrow + mt * 16 + g;
                int r1 = r0 + 8;
                sm[pfrag_w(FS_T, r0, col    )] = __float_as_uint(fmaxf(acc1[mt][nt][0] + bv0, 0.0f));
                sm[pfrag_w(FS_T, r0, col + 1)] = __float_as_uint(fmaxf(acc1[mt][nt][1] + bv1, 0.0f));
                sm[pfrag_w(FS_T, r1, col    )] = __float_as_uint(fmaxf(acc1[mt][nt][2] + bv0, 0.0f));
                sm[pfrag_w(FS_T, r1, col + 1)] = __float_as_uint(fmaxf(acc1[mt][nt][3] + bv1, 0.0f));
            }
        }
        __syncthreads();

        // ---- stage2: acc2 += t @ W5sub (128x64, K=64) ----
        #pragma unroll
        for (int ks = 0; ks < 8; ks++) {
            const int k0 = ks * 8;
            uint4 a[2];
            #pragma unroll
            for (int mt = 0; mt < 2; mt++)
                a[mt] = *(const uint4*)&sm[FS_T + pfrag_u4(ks, tg, wm * 2 + mt, g)];
            #pragma unroll
            for (int nt = 0; nt < 2; nt++) {
                int nc = wn * 16 + nt * 8 + g;
                unsigned int b0 = sm[FS_W5 + (k0 + tg    ) * 72 + nc];
                unsigned int b1 = sm[FS_W5 + (k0 + tg + 4) * 72 + nc];
                #pragma unroll
                for (int mt = 0; mt < 2; mt++)
                    mma_tf32(acc2[mt][nt], a[mt].x, a[mt].y, a[mt].z, a[mt].w, b0, b1);
            }
        }
    }
    __syncthreads();   // final stage2 done with FS_T / FS_W5 / FS_W4

    // ---- fc staging: Wf -> FS_W4, bf -> FS_B4; g3 (+b5) -> fragment-packed FS_T ----
    for (int i = tid; i < 64 * 40; i += FT) sm[FS_W4 + i] = __float_as_uint(Wf[i]);
    if (tid < 40) sm[FS_B4 + tid] = __float_as_uint(bf[tid]);
    #pragma unroll
    for (int nt = 0; nt < 2; nt++) {
        int col = wn * 16 + nt * 8 + 2 * tg;
        float bv0 = __uint_as_float(sm[FS_B5 + col]);
        float bv1 = __uint_as_float(sm[FS_B5 + col + 1]);
        #pragma unroll
        for (int mt = 0; mt < 2; mt++) {
            int r0 = mrow + mt * 16 + g;
            int r1 = r0 + 8;
            sm[pfrag_w(FS_T, r0, col    )] = __float_as_uint(acc2[mt][nt][0] + bv0);
            sm[pfrag_w(FS_T, r0, col + 1)] = __float_as_uint(acc2[mt][nt][1] + bv1);
            sm[pfrag_w(FS_T, r1, col    )] = __float_as_uint(acc2[mt][nt][2] + bv0);
            sm[pfrag_w(FS_T, r1, col + 1)] = __float_as_uint(acc2[mt][nt][3] + bv1);
        }
    }
    __syncthreads();

    // ---- fc + log_softmax: 16 warps x 8 nodes (reads are per-(node,k) broadcasts) ----
    for (int j = 0; j < 8; j++) {
        int nl = warp * 8 + j;
        int node = n0 + nl;
        if (node >= nrows) break;
        float v0 = __uint_as_float(sm[FS_B4 + lane]);
        float v1 = (lane < 8) ? __uint_as_float(sm[FS_B4 + lane + 32]) : -FLT_MAX;
        #pragma unroll
        for (int k = 0; k < 64; k++) {
            float a = fmaxf(__uint_as_float(sm[pfrag_w(FS_T, nl, k)]), 0.0f);
            float w0 = __uint_as_float(sm[FS_W4 + k * 40 + lane]);
            v0 = fmaf(a, w0, v0);
            if (lane < 8) {
                float w1 = __uint_as_float(sm[FS_W4 + k * 40 + lane + 32]);
                v1 = fmaf(a, w1, v1);
            }
        }
        float mx = fmaxf(v0, v1);
        #pragma unroll
        for (int off = 16; off > 0; off >>= 1)
            mx = fmaxf(mx, __shfl_xor_sync(0xFFFFFFFFu, mx, off));
        float s = __expf(v0 - mx) + ((lane < 8) ? __expf(v1 - mx) : 0.0f);
        #pragma unroll
        for (int off = 16; off > 0; off >>= 1)
            s += __shfl_xor_sync(0xFFFFFFFFu, s, off);
        float ls = __logf(s);
        float* op = out + (size_t)node * C_OUT;
        op[lane] = v0 - mx - ls;
        if (lane < 8) op[lane + 32] = v1 - mx - ls;
    }
}

// ---------------- launcher ----------------
extern "C" void kernel_launch(void* const* d_in, const int* in_sizes, int n_in,
                              void* d_out, int out_size) {
    const float* x   = (const float*)d_in[0];
    const float* pos = (const float*)d_in[1];
    const int*   ei  = (const int*)d_in[2];
    const float* W1 = (const float*)d_in[3];
    const float* b1 = (const float*)d_in[4];
    const float* W2 = (const float*)d_in[5];
    const float* b2 = (const float*)d_in[6];
    const float* W3 = (const float*)d_in[7];
    const float* b3 = (const float*)d_in[8];
    const float* W4 = (const float*)d_in[9];
    const float* b4 = (const float*)d_in[10];
    const float* W5 = (const float*)d_in[11];
    const float* b5 = (const float*)d_in[12];
    const float* Wf = (const float*)d_in[13];
    const float* bf = (const float*)d_in[14];
    float* out = (float*)d_out;

    void* aggp = nullptr;
    cudaGetSymbolAddress(&aggp, g_agg_u);

    cudaFuncSetAttribute(k_fused_mid, cudaFuncAttributeMaxDynamicSharedMemorySize,
                         FS_WORDS * 4);

    // mapped-uint 0 is below every mapped float -> -inf init
    cudaMemsetAsync(aggp, 0, (size_t)N_NODES * 64 * sizeof(unsigned int));

    k_edge_v4<<<(N_MSG + 255) / 256, 256>>>(x, pos, ei, W1, b1, W2, b2);

    k_fused_mid<<<(N_NODES + 127) / 128, FT, FS_WORDS * 4>>>(
        (const unsigned int*)aggp, W3, b3, W4, b4, W5, b5, Wf, bf, out, N_NODES);
}